// round 13
// baseline (speedup 1.0000x reference)
#include <cuda_runtime.h>
#include <math.h>
#include <cstdint>

// Problem constants
#define HW    4096
#define CC    320
#define CX    768
#define LKV   77
#define DH    40
#define NHEAD 8
#define NBATCH 10
#define NINST 8

// ======================= scratch (allocation is banned) ======================
__device__ float g_Q[2 * HW * CC];
__device__ float g_K[NBATCH * LKV * CC];
__device__ float g_V[NBATCH * LKV * CC];
__device__ float g_final[2 * HW * CC];
__device__ float g_bscale[HW];
__device__ float g_sinv[HW];
__device__ float g_hid_r[2 * HW * CC];
__device__ float g_ehs_r[NBATCH * LKV * CX];
__device__ float g_Wq_r[CC * CC];
__device__ float g_Wk_r[CX * CC];
__device__ float g_Wv_r[CX * CC];
__device__ float g_Wo_r[CC * CC];

// ======================= tf32 / mma helpers ==================================
__device__ __forceinline__ float tf32r(float v) {
    uint32_t t;
    asm("cvt.rna.tf32.f32 %0, %1;" : "=r"(t) : "f"(v));
    return __uint_as_float(t);
}
__device__ __forceinline__ void mma_tf32(float c[4], const uint32_t a[4], const uint32_t b[2]) {
    asm volatile(
        "mma.sync.aligned.m16n8k8.row.col.f32.tf32.tf32.f32 "
        "{%0,%1,%2,%3}, {%4,%5,%6,%7}, {%8,%9}, {%0,%1,%2,%3};"
        : "+f"(c[0]), "+f"(c[1]), "+f"(c[2]), "+f"(c[3])
        : "r"(a[0]), "r"(a[1]), "r"(a[2]), "r"(a[3]), "r"(b[0]), "r"(b[1]));
}
__device__ __forceinline__ void ldsm_x2(uint32_t& r0, uint32_t& r1, uint32_t addr) {
    asm volatile("ldmatrix.sync.aligned.m8n8.x2.shared.b16 {%0,%1}, [%2];"
                 : "=r"(r0), "=r"(r1) : "r"(addr));
}
__device__ __forceinline__ uint32_t smem_u32(const void* p) {
    return (uint32_t)__cvta_generic_to_shared(p);
}
__device__ __forceinline__ void cp16(uint32_t dst, const void* src, uint32_t sz) {
    asm volatile("cp.async.cg.shared.global [%0], [%1], 16, %2;"
                 :: "r"(dst), "l"(src), "r"(sz) : "memory");
}
#define CP_COMMIT() asm volatile("cp.async.commit_group;" ::: "memory")
#define CP_WAIT1()  asm volatile("cp.async.wait_group 1;" ::: "memory")
#define CP_WAIT0()  asm volatile("cp.async.wait_group 0;" ::: "memory")

// ======================= pre-round pass (fp32 -> tf32 rna) ===================
#define SEG0 (2 * HW * CC)
#define SEG1 (SEG0 + NBATCH * LKV * CX)
#define SEG2 (SEG1 + CC * CC)
#define SEG3 (SEG2 + CX * CC)
#define SEG4 (SEG3 + CX * CC)
#define SEG5 (SEG4 + CC * CC)

__global__ __launch_bounds__(256) void preround(
    const float* __restrict__ hid, const float* __restrict__ ehs,
    const float* __restrict__ Wq, const float* __restrict__ Wk,
    const float* __restrict__ Wv, const float* __restrict__ Wo,
    float* __restrict__ hid_r, float* __restrict__ ehs_r,
    float* __restrict__ wq_r, float* __restrict__ wk_r,
    float* __restrict__ wv_r, float* __restrict__ wo_r)
{
    const float scale = 0.15811388300841897f;  // 1/sqrt(40) folded into Wq
    int idx = blockIdx.x * 256 + threadIdx.x;
    if (idx < SEG0)       hid_r[idx]        = tf32r(hid[idx]);
    else if (idx < SEG1)  ehs_r[idx - SEG0] = tf32r(ehs[idx - SEG0]);
    else if (idx < SEG2)  wq_r[idx - SEG1]  = tf32r(Wq[idx - SEG1] * scale);
    else if (idx < SEG3)  wk_r[idx - SEG2]  = tf32r(Wk[idx - SEG2]);
    else if (idx < SEG4)  wv_r[idx - SEG3]  = tf32r(Wv[idx - SEG3]);
    else if (idx < SEG5)  wo_r[idx - SEG4]  = tf32r(Wo[idx - SEG4]);
}

// ======================= separable antialiased resize weight =================
__device__ __forceinline__ float axis_weight(int o, float lo, float hi)
{
    float c = 8.0f * o + 3.5f;
    int j0 = 8 * o - 4; if (j0 < 0) j0 = 0;
    int j1 = 8 * o + 11; if (j1 > 511) j1 = 511;
    float wsum = 0.0f, win = 0.0f;
    for (int j = j0; j <= j1; ++j) {
        float w = 1.0f - fabsf((float)j - c) * 0.125f;
        wsum += w;
        float jf = (float)j;
        if (jf >= lo && jf < hi) win += w;
    }
    return win / wsum;
}

// ======================= prep: zero fused half + sinv/bscale =================
#define PREP_N (HW * CC + HW)
__global__ __launch_bounds__(256) void prep_kernel(
    const float* __restrict__ bboxes, float* __restrict__ final_in,
    float* __restrict__ sinv, float* __restrict__ bscale)
{
    int idx = blockIdx.x * 256 + threadIdx.x;
    if (idx < HW * CC) {
        final_in[HW * CC + idx] = 0.0f;
    } else if (idx < PREP_N) {
        int pos = idx - HW * CC;
        int y = pos >> 6, x = pos & 63;
        float s = 0.1f;
        for (int n = 0; n < NINST; ++n) {
            const float* bb = bboxes + n * 4;
            float wmin = floorf(512.0f * bb[0]);
            float hmin = floorf(512.0f * bb[1]);
            float wmax = floorf(512.0f * bb[2]);
            float hmax = floorf(512.0f * bb[3]);
            s += axis_weight(y, hmin, hmax) * axis_weight(x, wmin, wmax) * 10.0f;
        }
        float iv = 1.0f / (s + 1e-6f);
        sinv[pos] = iv;
        bscale[pos] = s * iv;
    }
}

// ======================= tf32 GEMM, cp.async double-buffered (R11-proven) ====
#define AST 36
#define BST 72
#define STAGE_F (128 * AST + 32 * BST)
#define GSMEM (2 * STAGE_F * 4)

__global__ __launch_bounds__(256) void gemm_tf32(
    const float* __restrict__ A, const float* __restrict__ W, float* __restrict__ Cm,
    int M, int K,
    const float* __restrict__ W2, float* __restrict__ Cm2, int nxblk,
    const float* __restrict__ bias, const float* __restrict__ bscale, int mode)
{
    extern __shared__ float sm[];
    int bx = blockIdx.x;
    if (W2 != nullptr && bx >= nxblk) { W = W2; Cm = Cm2; bx -= nxblk; }

    int tid = threadIdx.x;
    int wid = tid >> 5, lane = tid & 31;
    int g = lane >> 2, tg = lane & 3;
    int wm = wid & 3, wn = wid >> 2;
    int m0 = blockIdx.y * 128, n0 = bx * 64;
    int NC = K / 32;

    uint32_t smb = smem_u32(sm);

    float c[2][4][4];
#pragma unroll
    for (int i = 0; i < 2; ++i)
#pragma unroll
        for (int j = 0; j < 4; ++j)
#pragma unroll
            for (int f = 0; f < 4; ++f) c[i][j][f] = 0.0f;

    auto load_stage = [&](int kc, int buf) {
        uint32_t base = smb + buf * STAGE_F * 4;
        int k0 = kc * 32;
#pragma unroll
        for (int i = 0; i < 4; ++i) {
            int idx = i * 256 + tid;
            int r = idx >> 3, c4 = idx & 7;
            int row = m0 + r;
            const float* src = A + (size_t)min(row, M - 1) * K + k0 + c4 * 4;
            cp16(base + (r * AST + c4 * 4) * 4, src, row < M ? 16u : 0u);
        }
#pragma unroll
        for (int i = 0; i < 2; ++i) {
            int idx = i * 256 + tid;
            int kr = idx >> 4, c4 = idx & 15;
            const float* src = W + (size_t)(k0 + kr) * CC + n0 + c4 * 4;
            cp16(base + (128 * AST + kr * BST + c4 * 4) * 4, src, 16u);
        }
        CP_COMMIT();
    };

    load_stage(0, 0);

    for (int kc = 0; kc < NC; ++kc) {
        int buf = kc & 1;
        if (kc + 1 < NC) { load_stage(kc + 1, (kc + 1) & 1); CP_WAIT1(); }
        else CP_WAIT0();
        __syncthreads();

        const float* As = sm + buf * STAGE_F;
        const float* Bs = As + 128 * AST;
#pragma unroll
        for (int k8 = 0; k8 < 4; ++k8) {
            int kb = k8 * 8;
            uint32_t a[2][4], b[4][2];
#pragma unroll
            for (int i = 0; i < 2; ++i) {
                int mb = (wm * 32 + i * 16 + g) * AST + kb + tg;
                a[i][0] = __float_as_uint(As[mb]);
                a[i][1] = __float_as_uint(As[mb + 8 * AST]);
                a[i][2] = __float_as_uint(As[mb + 4]);
                a[i][3] = __float_as_uint(As[mb + 8 * AST + 4]);
            }
#pragma unroll
            for (int j = 0; j < 4; ++j) {
                int nb = wn * 32 + j * 8 + g;
                b[j][0] = __float_as_uint(Bs[(kb + tg) * BST + nb]);
                b[j][1] = __float_as_uint(Bs[(kb + tg + 4) * BST + nb]);
            }
#pragma unroll
            for (int i = 0; i < 2; ++i)
#pragma unroll
                for (int j = 0; j < 4; ++j)
                    mma_tf32(c[i][j], a[i], b[j]);
        }
        __syncthreads();
    }

#pragma unroll
    for (int i = 0; i < 2; ++i) {
        int r0 = m0 + wm * 32 + i * 16 + g;
#pragma unroll
        for (int j = 0; j < 4; ++j) {
            int col = n0 + wn * 32 + j * 8 + 2 * tg;
#pragma unroll
            for (int h = 0; h < 2; ++h) {
                int row = r0 + h * 8;
                if (row >= M) continue;
                float v0 = c[i][j][h * 2 + 0];
                float v1 = c[i][j][h * 2 + 1];
                if (mode == 1) {
                    float bs = (row < HW) ? 1.0f : bscale[row - HW];
                    v0 += bias[col] * bs;
                    v1 += bias[col + 1] * bs;
                } else if (mode == 2) {
                    v0 = tf32r(v0);
                    v1 = tf32r(v1);
                }
                *reinterpret_cast<float2*>(Cm + (size_t)row * CC + col) = make_float2(v0, v1);
            }
        }
    }
}

// ======================= attention: 32-row warps + fused atomic reduce =======
// 4 warps/block, each owns 32 q-rows (2 A-frag row groups sharing every B-frag).
// Cond batches (b>=1) atomically accumulate w*sinv-scaled output into the
// fused half of final_in. Uncond (b==0) writes its half directly.
#define KST  44
#define VTST 84
#define ATTN_SMEM ((80 * KST + 40 * VTST) * 4)

__global__ __launch_bounds__(128, 3) void attn_kernel(
    const float* __restrict__ Q, const float* __restrict__ K, const float* __restrict__ V,
    const float* __restrict__ bboxes, const float* __restrict__ sinv,
    float* __restrict__ final_in)
{
    extern __shared__ float sm[];
    float* Ks = sm;                 // [80][KST]
    float* Vt = sm + 80 * KST;      // [40][VTST]

    int qt = blockIdx.x, h = blockIdx.y, b = blockIdx.z;
    int tid = threadIdx.x;
    int wid = tid >> 5, lane = tid & 31;
    int g = lane >> 2, tg = lane & 3;
    int q0 = qt * 128;
    int r0 = q0 >> 6;

    float wmin = 0.f, wmax = 0.f, hmin = 0.f, hmax = 0.f;
    if (b >= 2) {
        const float* bb = bboxes + (b - 2) * 4;
        wmin = floorf(512.0f * bb[0]);
        hmin = floorf(512.0f * bb[1]);
        wmax = floorf(512.0f * bb[2]);
        hmax = floorf(512.0f * bb[3]);
        float j0 = fmaxf(0.0f, 8.0f * r0 - 4.0f);
        float j1 = fminf(511.0f, 8.0f * r0 + 19.0f);
        if (fmaxf(j0, hmin) > fminf(j1, hmax - 1.0f)) return;
    }

    // cooperative K/V load; V stored transposed; rows 77..79 zero-padded.
    const float* Kb = K + (size_t)b * LKV * CC + h * DH;
    const float* Vb = V + (size_t)b * LKV * CC + h * DH;
    for (int idx = tid; idx < 80 * DH; idx += 128) {
        int r = idx / DH, cc = idx - r * DH;
        float kv = 0.f, vv = 0.f;
        if (r < LKV) { kv = Kb[(size_t)r * CC + cc]; vv = Vb[(size_t)r * CC + cc]; }
        Ks[r * KST + cc] = kv;
        Vt[cc * VTST + r] = vv;
    }
    __syncthreads();

    // warp geometry: 32 rows, one image row y, 32-col x window
    int rb = wid * 32;
    int wy = r0 + (wid >> 1);
    int wx0 = (wid & 1) * 32;

    float ay = 1.0f;
    if (b >= 2) {
        float jy0 = fmaxf(0.0f, 8.0f * wy - 4.0f);
        float jy1 = fminf(511.0f, 8.0f * wy + 11.0f);
        bool ok = fmaxf(jy0, hmin) <= fminf(jy1, hmax - 1.0f);
        float jx0 = fmaxf(0.0f, 8.0f * wx0 - 4.0f);
        float jx1 = fminf(511.0f, 8.0f * (wx0 + 31) + 11.0f);
        ok = ok && (fmaxf(jx0, wmin) <= fminf(jx1, wmax - 1.0f));
        if (!ok) return;
        ay = axis_weight(wy, hmin, hmax);
    }

    int qb = (b == 0) ? 0 : 1;
    const float* Qg = Q + ((size_t)qb * HW + q0 + rb) * CC + h * DH;

    uint32_t kbase = smem_u32(Ks) + (((lane & 7) * KST + ((lane >> 3) & 1) * 4) * 4);
    uint32_t vbase = smem_u32(Vt) + (((lane & 7) * VTST + ((lane >> 3) & 1) * 4) * 4);

    // ---------------- QK^T: two 16x80 tiles sharing K fragments ----------------
    float c[2][10][4];
#pragma unroll
    for (int i = 0; i < 2; ++i)
#pragma unroll
        for (int j = 0; j < 10; ++j)
#pragma unroll
            for (int f = 0; f < 4; ++f) c[i][j][f] = 0.0f;

#pragma unroll
    for (int k5 = 0; k5 < 5; ++k5) {
        int kb = k5 * 8;
        uint32_t a[2][4];
#pragma unroll
        for (int i = 0; i < 2; ++i) {
            const float* Qi = Qg + (size_t)(i * 16) * CC;
            a[i][0] = __float_as_uint(Qi[(size_t)g * CC + kb + tg]);
            a[i][1] = __float_as_uint(Qi[(size_t)(g + 8) * CC + kb + tg]);
            a[i][2] = __float_as_uint(Qi[(size_t)g * CC + kb + tg + 4]);
            a[i][3] = __float_as_uint(Qi[(size_t)(g + 8) * CC + kb + tg + 4]);
        }
#pragma unroll
        for (int j = 0; j < 10; ++j) {
            uint32_t bfr[2];
            ldsm_x2(bfr[0], bfr[1], kbase + (j * 8 * KST + kb) * 4);
            mma_tf32(c[0][j], a[0], bfr);
            mma_tf32(c[1][j], a[1], bfr);
        }
    }

    // ---------------- softmax ----------------
    float l[2][2] = {{0.f, 0.f}, {0.f, 0.f}};
#pragma unroll
    for (int i = 0; i < 2; ++i) {
#pragma unroll
        for (int j = 0; j < 10; ++j) {
#pragma unroll
            for (int e = 0; e < 2; ++e) {
                int col = j * 8 + 2 * tg + e;
                float p0 = (col < LKV) ? __expf(c[i][j][e]) : 0.0f;
                float p1 = (col < LKV) ? __expf(c[i][j][2 + e]) : 0.0f;
                p0 = tf32r(p0); p1 = tf32r(p1);
                c[i][j][e] = p0; c[i][j][2 + e] = p1;
                l[i][0] += p0; l[i][1] += p1;
            }
        }
        l[i][0] += __shfl_xor_sync(0xFFFFFFFF, l[i][0], 1);
        l[i][0] += __shfl_xor_sync(0xFFFFFFFF, l[i][0], 2);
        l[i][1] += __shfl_xor_sync(0xFFFFFFFF, l[i][1], 1);
        l[i][1] += __shfl_xor_sync(0xFFFFFFFF, l[i][1], 2);
    }

    // ---------------- PV: shuffle-transpose P, V fragments shared over i -------
    float o[2][5][4];
#pragma unroll
    for (int i = 0; i < 2; ++i)
#pragma unroll
        for (int j2 = 0; j2 < 5; ++j2)
#pragma unroll
            for (int f = 0; f < 4; ++f) o[i][j2][f] = 0.0f;

    int s0 = (lane & ~3) | (tg >> 1);
    int s1 = s0 + 2;
    bool oddc = (tg & 1);

#pragma unroll
    for (int k10 = 0; k10 < 10; ++k10) {
        uint32_t pa[2][4];
#pragma unroll
        for (int i = 0; i < 2; ++i) {
            float x0 = __shfl_sync(0xFFFFFFFF, c[i][k10][0], s0);
            float x1 = __shfl_sync(0xFFFFFFFF, c[i][k10][1], s0);
            float y0 = __shfl_sync(0xFFFFFFFF, c[i][k10][0], s1);
            float y1 = __shfl_sync(0xFFFFFFFF, c[i][k10][1], s1);
            float z0 = __shfl_sync(0xFFFFFFFF, c[i][k10][2], s0);
            float z1 = __shfl_sync(0xFFFFFFFF, c[i][k10][3], s0);
            float u0 = __shfl_sync(0xFFFFFFFF, c[i][k10][2], s1);
            float u1 = __shfl_sync(0xFFFFFFFF, c[i][k10][3], s1);
            pa[i][0] = __float_as_uint(oddc ? x1 : x0);
            pa[i][1] = __float_as_uint(oddc ? z1 : z0);
            pa[i][2] = __float_as_uint(oddc ? y1 : y0);
            pa[i][3] = __float_as_uint(oddc ? u1 : u0);
        }
#pragma unroll
        for (int j2 = 0; j2 < 5; ++j2) {
            uint32_t bfr[2];
            ldsm_x2(bfr[0], bfr[1], vbase + (j2 * 8 * VTST + k10 * 8) * 4);
            mma_tf32(o[0][j2], pa[0], bfr);
            mma_tf32(o[1][j2], pa[1], bfr);
        }
    }

    // ---------------- write out ----------------
#pragma unroll
    for (int i = 0; i < 2; ++i) {
#pragma unroll
        for (int h2 = 0; h2 < 2; ++h2) {
            int local = rb + 16 * i + 8 * h2 + g;
            int pos = q0 + local;
            float inv = 1.0f / l[i][h2];
            if (b == 0) {
                float* dst = final_in + (size_t)pos * CC + h * DH;
#pragma unroll
                for (int j2 = 0; j2 < 5; ++j2) {
                    int col = j2 * 8 + 2 * tg;
                    *reinterpret_cast<float2*>(dst + col) = make_float2(
                        tf32r(o[i][j2][h2 * 2 + 0] * inv),
                        tf32r(o[i][j2][h2 * 2 + 1] * inv));
                }
            } else {
                float wv = 0.1f;
                if (b >= 2) wv = ay * axis_weight(local & 63, wmin, wmax) * 10.0f;
                if (wv != 0.0f) {
                    float sc = wv * sinv[pos] * inv;
                    float* dst = final_in + (size_t)(HW + pos) * CC + h * DH;
#pragma unroll
                    for (int j2 = 0; j2 < 5; ++j2) {
                        int col = j2 * 8 + 2 * tg;
                        atomicAdd(dst + col,     o[i][j2][h2 * 2 + 0] * sc);
                        atomicAdd(dst + col + 1, o[i][j2][h2 * 2 + 1] * sc);
                    }
                }
            }
        }
    }
}

// ======================= launch ==============================================
extern "C" void kernel_launch(void* const* d_in, const int* in_sizes, int n_in,
                              void* d_out, int out_size)
{
    const float* hidden = (const float*)d_in[0];
    const float* ehs    = (const float*)d_in[1];
    const float* bbox   = (const float*)d_in[2];
    const float* Wq     = (const float*)d_in[3];
    const float* Wk     = (const float*)d_in[4];
    const float* Wv     = (const float*)d_in[5];
    const float* Wo     = (const float*)d_in[6];
    const float* bo     = (const float*)d_in[7];
    float* out = (float*)d_out;

    float *Qp, *Kp, *Vp, *Fp, *Bp, *Sp, *Hr, *Er, *Wqr, *Wkr, *Wvr, *Wor;
    cudaGetSymbolAddress((void**)&Qp, g_Q);
    cudaGetSymbolAddress((void**)&Kp, g_K);
    cudaGetSymbolAddress((void**)&Vp, g_V);
    cudaGetSymbolAddress((void**)&Fp, g_final);
    cudaGetSymbolAddress((void**)&Bp, g_bscale);
    cudaGetSymbolAddress((void**)&Sp, g_sinv);
    cudaGetSymbolAddress((void**)&Hr, g_hid_r);
    cudaGetSymbolAddress((void**)&Er, g_ehs_r);
    cudaGetSymbolAddress((void**)&Wqr, g_Wq_r);
    cudaGetSymbolAddress((void**)&Wkr, g_Wk_r);
    cudaGetSymbolAddress((void**)&Wvr, g_Wv_r);
    cudaGetSymbolAddress((void**)&Wor, g_Wo_r);

    cudaFuncSetAttribute(gemm_tf32, cudaFuncAttributeMaxDynamicSharedMemorySize, GSMEM);
    cudaFuncSetAttribute(attn_kernel, cudaFuncAttributeMaxDynamicSharedMemorySize, ATTN_SMEM);

    // 1) round activations + weights to tf32 once (scale folded into Wq)
    preround<<<(SEG5 + 255) / 256, 256>>>(hidden, ehs, Wq, Wk, Wv, Wo,
                                          Hr, Er, Wqr, Wkr, Wvr, Wor);

    // 2) zero fused accumulator + per-position sinv/bscale
    prep_kernel<<<(PREP_N + 255) / 256, 256>>>(bbox, Fp, Sp, Bp);

    // 3) Q projection (pipelined tf32 MMA), tf32-rounded output
    gemm_tf32<<<dim3(5, 64), 256, GSMEM>>>(
        Hr, Wqr, Qp, 2 * HW, CC, nullptr, nullptr, 1 << 30, nullptr, nullptr, 2);

    // 4) fused K+V projection: blocks 0-4 -> K, 5-9 -> V
    gemm_tf32<<<dim3(10, 7), 256, GSMEM>>>(
        Er, Wkr, Kp, NBATCH * LKV, CX, Wvr, Vp, 5, nullptr, nullptr, 2);

    // 5) attention: 32-row warps, B-frag reuse, fused atomic weighted reduce
    attn_kernel<<<dim3(HW / 128, NHEAD, NBATCH), 128, ATTN_SMEM>>>(
        Qp, Kp, Vp, bbox, Sp, Fp);

    // 6) output projection + bias epilogue
    gemm_tf32<<<dim3(5, 64), 256, GSMEM>>>(
        Fp, Wor, out, 2 * HW, CC, nullptr, nullptr, 1 << 30, bo, Bp, 1);
}